// round 1
// baseline (speedup 1.0000x reference)
#include <cuda_runtime.h>
#include <cuda_bf16.h>

#define BATCH 2
#define SEQ   2048
#define DM    1024
#define NH    16
#define DH    64
#define KS    32
#define TQ    8

#define MROWS (BATCH*SEQ)   // 4096

// ---------------- scratch (device globals; no allocation allowed) ----------
__device__ float g_Q [BATCH*SEQ*DM];
__device__ float g_K [BATCH*SEQ*DM];
__device__ float g_V [BATCH*SEQ*DM];
__device__ float g_HO[BATCH*SEQ*DM];
__device__ float g_WGT[BATCH*NH*SEQ*KS];
__device__ int   g_IDX[BATCH*NH*SEQ*KS];

__device__ __forceinline__ float neg_inf() { return __int_as_float(0xff800000); }

// ---------------- GEMM: C[M,N] = A[M,K] @ W[N,K]^T + bias --------------------
#define BM 128
#define BN 128
#define BK 8

__global__ __launch_bounds__(256) void gemm_kernel(
    const float* __restrict__ A, const float* __restrict__ W,
    const float* __restrict__ bias, float* __restrict__ C,
    int M, int N, int K)
{
    __shared__ float As[BK][BM];
    __shared__ float Ws[BK][BN];
    int tid = threadIdx.x;
    int tx = tid & 15, ty = tid >> 4;
    int bm = blockIdx.y * BM, bn = blockIdx.x * BN;

    float acc[8][8];
#pragma unroll
    for (int i = 0; i < 8; i++)
#pragma unroll
        for (int j = 0; j < 8; j++) acc[i][j] = 0.f;

    int lr = tid >> 1;            // 0..127
    int lc = (tid & 1) * 4;       // 0 or 4

    for (int k0 = 0; k0 < K; k0 += BK) {
        float4 av = *(const float4*)(A + (size_t)(bm + lr) * K + k0 + lc);
        float4 wv = *(const float4*)(W + (size_t)(bn + lr) * K + k0 + lc);
        As[lc+0][lr] = av.x; As[lc+1][lr] = av.y; As[lc+2][lr] = av.z; As[lc+3][lr] = av.w;
        Ws[lc+0][lr] = wv.x; Ws[lc+1][lr] = wv.y; Ws[lc+2][lr] = wv.z; Ws[lc+3][lr] = wv.w;
        __syncthreads();
#pragma unroll
        for (int kk = 0; kk < BK; kk++) {
            float4 a0 = *(const float4*)&As[kk][ty*4];
            float4 a1 = *(const float4*)&As[kk][64 + ty*4];
            float4 w0 = *(const float4*)&Ws[kk][tx*4];
            float4 w1 = *(const float4*)&Ws[kk][64 + tx*4];
            float a[8] = {a0.x,a0.y,a0.z,a0.w,a1.x,a1.y,a1.z,a1.w};
            float w[8] = {w0.x,w0.y,w0.z,w0.w,w1.x,w1.y,w1.z,w1.w};
#pragma unroll
            for (int i = 0; i < 8; i++)
#pragma unroll
                for (int j = 0; j < 8; j++)
                    acc[i][j] += a[i] * w[j];
        }
        __syncthreads();
    }

    float4 b0 = *(const float4*)(bias + bn + tx*4);
    float4 b1 = *(const float4*)(bias + bn + 64 + tx*4);
    float bb[8] = {b0.x,b0.y,b0.z,b0.w,b1.x,b1.y,b1.z,b1.w};

#pragma unroll
    for (int i = 0; i < 8; i++) {
        int m = bm + ((i < 4) ? (ty*4 + i) : (64 + ty*4 + i - 4));
        float4 o0 = make_float4(acc[i][0]+bb[0], acc[i][1]+bb[1], acc[i][2]+bb[2], acc[i][3]+bb[3]);
        float4 o1 = make_float4(acc[i][4]+bb[4], acc[i][5]+bb[5], acc[i][6]+bb[6], acc[i][7]+bb[7]);
        *(float4*)(C + (size_t)m * N + bn + tx*4)      = o0;
        *(float4*)(C + (size_t)m * N + bn + 64 + tx*4) = o1;
    }
}

// ---------------- attention: scores + top-32 + softmax + AV ------------------
// Block handles TQ=8 consecutive queries for one (b,h). 256 threads.
// Dynamic smem: scores [TQ][SEQ] = 64 KB.
__global__ __launch_bounds__(256) void attn_kernel(
    const float* __restrict__ Q, const float* __restrict__ Kg,
    const float* __restrict__ Vg, float* __restrict__ HO,
    float* __restrict__ WGT, int* __restrict__ IDX)
{
    extern __shared__ float s_scores[];   // [TQ][SEQ]
    __shared__ float s_q[TQ][DH];
    __shared__ float s_w[TQ][KS];
    __shared__ int   s_i[TQ][KS];

    const int tile = blockIdx.x;
    const int h = blockIdx.y, b = blockIdx.z;
    const int q0 = tile * TQ;
    const int tid = threadIdx.x;
    const int lane = tid & 31, wid = tid >> 5;
    const float NEG = neg_inf();

    // load 8 query vectors
    for (int i = tid; i < TQ*DH; i += 256) {
        int qi = i >> 6, d = i & 63;
        s_q[qi][d] = Q[((size_t)(b*SEQ + q0 + qi)) * DM + h*DH + d];
    }
    __syncthreads();

    const int nkmax = q0 + TQ;   // keys 0 .. q0+TQ-1 cover all causal needs
    const float* Kb = Kg + (size_t)b*SEQ*DM + h*DH;

    // ---- scores: 4 lanes per key (each lane: 16 dims), coalesced 64B chunks
    const int sub = lane & 3;      // dim chunk
    const int kk8 = lane >> 3 ? 0 : 0; (void)kk8;
    const int kwi = lane >> 2;     // 0..7: key within group
    for (int kb = wid * 8; kb < nkmax; kb += 64) {
        int k = kb + kwi;
        float acc[TQ];
#pragma unroll
        for (int qi = 0; qi < TQ; qi++) acc[qi] = 0.f;
        if (k < nkmax) {
            const float4* kp = (const float4*)(Kb + (size_t)k * DM + sub*16);
#pragma unroll
            for (int c4 = 0; c4 < 4; c4++) {
                float4 kv = kp[c4];
                int dbase = sub*16 + c4*4;
#pragma unroll
                for (int qi = 0; qi < TQ; qi++) {
                    float4 qv = *(const float4*)&s_q[qi][dbase];
                    acc[qi] += kv.x*qv.x + kv.y*qv.y + kv.z*qv.z + kv.w*qv.w;
                }
            }
        }
#pragma unroll
        for (int qi = 0; qi < TQ; qi++) {
            acc[qi] += __shfl_xor_sync(0xffffffffu, acc[qi], 1);
            acc[qi] += __shfl_xor_sync(0xffffffffu, acc[qi], 2);
        }
        if (sub == 0 && k < nkmax) {
#pragma unroll
            for (int qi = 0; qi < TQ; qi++)
                s_scores[qi*SEQ + k] = acc[qi] * 0.125f;
        }
    }
    __syncthreads();

    // ---- top-32 selection: warp `wid` owns query qi=wid
    {
        const int qi = wid;
        const int nk = q0 + qi + 1;
        float* sc = s_scores + qi*SEQ;
        for (int it = 0; it < KS; it++) {
            float bv = NEG; int bi = -1;
            for (int k = lane; k < nk; k += 32) {
                float v = sc[k];
                if (v > bv) { bv = v; bi = k; }   // ascending k: strict > keeps smallest index on ties
            }
#pragma unroll
            for (int o = 16; o; o >>= 1) {
                float ov = __shfl_down_sync(0xffffffffu, bv, o);
                int   oi = __shfl_down_sync(0xffffffffu, bi, o);
                if (ov > bv || (ov == bv && (unsigned)oi < (unsigned)bi)) { bv = ov; bi = oi; }
            }
            if (lane == 0) {
                s_w[qi][it] = bv;
                s_i[qi][it] = bi;
                if (bi >= 0) sc[bi] = NEG;
            }
            __syncwarp();
        }

        // ---- softmax over the 32 selected (lane j = entry j)
        float val = s_w[qi][lane];
        int   ii  = s_i[qi][lane];
        float m   = __shfl_sync(0xffffffffu, val, 0);   // first pick = max, finite
        float e   = (ii >= 0) ? expf(val - m) : 0.f;
        float tot = e;
#pragma unroll
        for (int o = 16; o; o >>= 1) tot += __shfl_xor_sync(0xffffffffu, tot, o);
        float w = e / tot;
        s_w[qi][lane] = w;
        size_t off = ((((size_t)b*NH + h)*SEQ) + (size_t)(q0 + qi)) * KS + lane;
        WGT[off] = w;
        IDX[off] = ii;
    }
    __syncthreads();

    // ---- AV: out[qi][d] = sum_j w_j * V[idx_j][d]
    for (int o = tid; o < TQ*DH; o += 256) {
        int qi = o >> 6, d = o & 63;
        const float* Vb = Vg + (size_t)b*SEQ*DM + h*DH + d;
        float acc = 0.f;
#pragma unroll
        for (int j = 0; j < KS; j++) {
            float w = s_w[qi][j];
            int ii = s_i[qi][j];
            if (ii >= 0) acc += w * Vb[(size_t)ii * DM];
        }
        HO[((size_t)(b*SEQ + q0 + qi)) * DM + h*DH + d] = acc;
    }
}

// ---------------- mean over heads -> dense [B, SEQ, SEQ] ---------------------
// Deterministic: serialize over heads (indices within one head are distinct).
__global__ __launch_bounds__(256) void mean_kernel(
    const float* __restrict__ WGT, const int* __restrict__ IDX,
    float* __restrict__ out_attn)
{
    __shared__ float row[SEQ];
    const int q = blockIdx.x, b = blockIdx.y;
    const int tid = threadIdx.x;
    for (int i = tid; i < SEQ; i += 256) row[i] = 0.f;
    __syncthreads();
    for (int h = 0; h < NH; h++) {
        if (tid < KS) {
            size_t off = ((((size_t)b*NH + h)*SEQ) + q) * KS + tid;
            float w = WGT[off];
            int k = IDX[off];
            if (k >= 0 && w > 0.f) row[k] += w * (1.0f / NH);
        }
        __syncthreads();
    }
    float* o = out_attn + ((size_t)b*SEQ + q) * SEQ;
    for (int i = tid; i < SEQ; i += 256) o[i] = row[i];
}

// ---------------- launch -----------------------------------------------------
extern "C" void kernel_launch(void* const* d_in, const int* in_sizes, int n_in,
                              void* d_out, int out_size)
{
    const float* x  = (const float*)d_in[0];
    const float* Wq = (const float*)d_in[1];
    const float* bq = (const float*)d_in[2];
    const float* Wk = (const float*)d_in[3];
    const float* bk = (const float*)d_in[4];
    const float* Wv = (const float*)d_in[5];
    const float* bv = (const float*)d_in[6];
    const float* Wo = (const float*)d_in[7];
    const float* bo = (const float*)d_in[8];

    float *Qp, *Kp, *Vp, *HOp, *Wp; int* Ip;
    cudaGetSymbolAddress((void**)&Qp,  g_Q);
    cudaGetSymbolAddress((void**)&Kp,  g_K);
    cudaGetSymbolAddress((void**)&Vp,  g_V);
    cudaGetSymbolAddress((void**)&HOp, g_HO);
    cudaGetSymbolAddress((void**)&Wp,  g_WGT);
    cudaGetSymbolAddress((void**)&Ip,  g_IDX);

    dim3 ggrid(DM / BN, MROWS / BM);   // (8, 32)

    gemm_kernel<<<ggrid, 256>>>(x, Wq, bq, Qp, MROWS, DM, DM);
    gemm_kernel<<<ggrid, 256>>>(x, Wk, bk, Kp, MROWS, DM, DM);
    gemm_kernel<<<ggrid, 256>>>(x, Wv, bv, Vp, MROWS, DM, DM);

    cudaFuncSetAttribute(attn_kernel, cudaFuncAttributeMaxDynamicSharedMemorySize,
                         TQ * SEQ * (int)sizeof(float));
    attn_kernel<<<dim3(SEQ / TQ, NH, BATCH), 256, TQ * SEQ * sizeof(float)>>>(
        Qp, Kp, Vp, HOp, Wp, Ip);

    float* yout = (float*)d_out;
    gemm_kernel<<<ggrid, 256>>>(HOp, Wo, bo, yout, MROWS, DM, DM);

    size_t ysz = (size_t)BATCH * SEQ * DM;          // 4,194,304
    size_t asz = (size_t)BATCH * SEQ * SEQ;         // 8,388,608
    if ((size_t)out_size >= ysz + asz) {
        mean_kernel<<<dim3(SEQ, BATCH), 256>>>(Wp, Ip, (float*)d_out + ysz);
    }
}

// round 2
// speedup vs baseline: 1.0254x; 1.0254x over previous
#include <cuda_runtime.h>
#include <cuda_bf16.h>

#define BATCH 2
#define SEQ   2048
#define DM    1024
#define NH    16
#define DH    64
#define KS    32
#define TQ    8
#define CCH   512           // score chunk (keys) staged in smem

#define MROWS (BATCH*SEQ)   // 4096
#define FULLM 0xffffffffu

// ---------------- scratch (device globals; no allocation allowed) ----------
__device__ float g_Q [BATCH*SEQ*DM];
__device__ float g_K [BATCH*SEQ*DM];
__device__ float g_V [BATCH*SEQ*DM];
__device__ float g_HO[BATCH*SEQ*DM];
__device__ float g_WGT[BATCH*NH*SEQ*KS];
__device__ int   g_IDX[BATCH*NH*SEQ*KS];

__device__ __forceinline__ float neg_inf() { return __int_as_float(0xff800000); }

// ---------------- GEMM: C[M,N] = A[M,K] @ W[N,K]^T + bias --------------------
#define BM 128
#define BN 128
#define BK 8

__global__ __launch_bounds__(256) void gemm_kernel(
    const float* __restrict__ A, const float* __restrict__ W,
    const float* __restrict__ bias, float* __restrict__ C,
    int M, int N, int K)
{
    __shared__ float As[BK][BM];
    __shared__ float Ws[BK][BN];
    int tid = threadIdx.x;
    int tx = tid & 15, ty = tid >> 4;
    int bm = blockIdx.y * BM, bn = blockIdx.x * BN;

    float acc[8][8];
#pragma unroll
    for (int i = 0; i < 8; i++)
#pragma unroll
        for (int j = 0; j < 8; j++) acc[i][j] = 0.f;

    int lr = tid >> 1;            // 0..127
    int lc = (tid & 1) * 4;       // 0 or 4

    for (int k0 = 0; k0 < K; k0 += BK) {
        float4 av = *(const float4*)(A + (size_t)(bm + lr) * K + k0 + lc);
        float4 wv = *(const float4*)(W + (size_t)(bn + lr) * K + k0 + lc);
        As[lc+0][lr] = av.x; As[lc+1][lr] = av.y; As[lc+2][lr] = av.z; As[lc+3][lr] = av.w;
        Ws[lc+0][lr] = wv.x; Ws[lc+1][lr] = wv.y; Ws[lc+2][lr] = wv.z; Ws[lc+3][lr] = wv.w;
        __syncthreads();
#pragma unroll
        for (int kk = 0; kk < BK; kk++) {
            float4 a0 = *(const float4*)&As[kk][ty*4];
            float4 a1 = *(const float4*)&As[kk][64 + ty*4];
            float4 w0 = *(const float4*)&Ws[kk][tx*4];
            float4 w1 = *(const float4*)&Ws[kk][64 + tx*4];
            float a[8] = {a0.x,a0.y,a0.z,a0.w,a1.x,a1.y,a1.z,a1.w};
            float w[8] = {w0.x,w0.y,w0.z,w0.w,w1.x,w1.y,w1.z,w1.w};
#pragma unroll
            for (int i = 0; i < 8; i++)
#pragma unroll
                for (int j = 0; j < 8; j++)
                    acc[i][j] += a[i] * w[j];
        }
        __syncthreads();
    }

    float4 b0 = *(const float4*)(bias + bn + tx*4);
    float4 b1 = *(const float4*)(bias + bn + 64 + tx*4);
    float bb[8] = {b0.x,b0.y,b0.z,b0.w,b1.x,b1.y,b1.z,b1.w};

#pragma unroll
    for (int i = 0; i < 8; i++) {
        int m = bm + ((i < 4) ? (ty*4 + i) : (64 + ty*4 + i - 4));
        float4 o0 = make_float4(acc[i][0]+bb[0], acc[i][1]+bb[1], acc[i][2]+bb[2], acc[i][3]+bb[3]);
        float4 o1 = make_float4(acc[i][4]+bb[4], acc[i][5]+bb[5], acc[i][6]+bb[6], acc[i][7]+bb[7]);
        *(float4*)(C + (size_t)m * N + bn + tx*4)      = o0;
        *(float4*)(C + (size_t)m * N + bn + 64 + tx*4) = o1;
    }
}

// ---------------- attention: scores + streaming top-32 + softmax + AV --------
// Block: 8 warps, warp w owns query q0+w. Scores staged in 512-key chunks.
// Top-32 kept in registers (1 (val,idx)/lane, sorted descending across lanes).
__global__ __launch_bounds__(256) void attn_kernel(
    const float* __restrict__ Q, const float* __restrict__ Kg,
    const float* __restrict__ Vg, float* __restrict__ HO,
    float* __restrict__ WGT, int* __restrict__ IDX)
{
    __shared__ float s_q[TQ][DH];
    __shared__ float s_chunk[TQ][CCH];
    __shared__ float s_w[TQ][KS];
    __shared__ int   s_i[TQ][KS];

    const int tile = blockIdx.x;
    const int h = blockIdx.y, b = blockIdx.z;
    const int q0 = tile * TQ;
    const int tid = threadIdx.x;
    const int lane = tid & 31, wid = tid >> 5;
    const int qglob = q0 + wid;
    const float NEG = neg_inf();

    // load 8 query vectors
    for (int i = tid; i < TQ*DH; i += 256) {
        int qi = i >> 6, d = i & 63;
        s_q[qi][d] = Q[((size_t)(b*SEQ + q0 + qi)) * DM + h*DH + d];
    }
    __syncthreads();

    const int nkmax = q0 + TQ;          // multiple of 8
    const float* Kb = Kg + (size_t)b*SEQ*DM + h*DH;

    // selection state: sorted descending by (val desc, idx asc)
    float sv = NEG;
    int   si = 0x7fffffff;

    const int sub = lane & 3;           // 16-dim chunk within key
    const int kwi = lane >> 2;          // key within 8-key group

    for (int kb = 0; kb < nkmax; kb += CCH) {
        const int climit = min(CCH, nkmax - kb);   // multiple of 8

        // ---- compute scores for keys [kb, kb+climit) into s_chunk ----
        for (int kk = wid * 8; kk < climit; kk += 64) {
            int k = kb + kk + kwi;
            float acc[TQ];
#pragma unroll
            for (int qi = 0; qi < TQ; qi++) acc[qi] = 0.f;
            const float4* kp = (const float4*)(Kb + (size_t)k * DM + sub*16);
#pragma unroll
            for (int c4 = 0; c4 < 4; c4++) {
                float4 kv = kp[c4];
                int dbase = sub*16 + c4*4;
#pragma unroll
                for (int qi = 0; qi < TQ; qi++) {
                    float4 qv = *(const float4*)&s_q[qi][dbase];
                    acc[qi] += kv.x*qv.x + kv.y*qv.y + kv.z*qv.z + kv.w*qv.w;
                }
            }
#pragma unroll
            for (int qi = 0; qi < TQ; qi++) {
                acc[qi] += __shfl_xor_sync(FULLM, acc[qi], 1);
                acc[qi] += __shfl_xor_sync(FULLM, acc[qi], 2);
            }
            if (sub == 0) {
#pragma unroll
                for (int qi = 0; qi < TQ; qi++)
                    s_chunk[qi][kk + kwi] = acc[qi] * 0.125f;
            }
        }
        __syncthreads();

        // ---- streaming selection over this chunk (warp -> its query) ----
        const int nb = (climit + 31) >> 5;
        for (int bi2 = 0; bi2 < nb; bi2++) {
            int kl = (bi2 << 5) + lane;
            int kg = kb + kl;
            float v = NEG; int ii = 0x7fffffff;
            if (kg <= qglob) { v = s_chunk[wid][kl]; ii = kg; }

            float minv = __shfl_sync(FULLM, sv, 31);
            int   mini = __shfl_sync(FULLM, si, 31);
            bool contend = (v > minv) || (v == minv && v != NEG && ii < mini);
            unsigned m = __ballot_sync(FULLM, contend);
            while (m) {
                int src = __ffs(m) - 1; m &= m - 1;
                float nv = __shfl_sync(FULLM, v,  src);
                int   ni = __shfl_sync(FULLM, ii, src);
                bool better = (sv > nv) || (sv == nv && si < ni);
                unsigned bm2 = __ballot_sync(FULLM, better);
                int p = __popc(bm2);
                float upv = __shfl_up_sync(FULLM, sv, 1);
                int   upi = __shfl_up_sync(FULLM, si, 1);
                if (lane == p)      { sv = nv;  si = ni;  }
                else if (lane > p)  { sv = upv; si = upi; }
            }
        }
        __syncthreads();   // protect s_chunk for next chunk
    }

    // ---- softmax over selected 32 ----
    {
        bool valid = (sv != NEG);
        float mx = __shfl_sync(FULLM, sv, 0);    // lane 0 = max, always finite
        float e = valid ? expf(sv - mx) : 0.f;
        float tot = e;
#pragma unroll
        for (int o = 16; o; o >>= 1) tot += __shfl_xor_sync(FULLM, tot, o);
        float w = e / tot;
        int iw = valid ? si : -1;
        s_w[wid][lane] = w;
        s_i[wid][lane] = iw;
        size_t off = ((((size_t)b*NH + h)*SEQ) + (size_t)qglob) * KS + lane;
        WGT[off] = w;
        IDX[off] = iw;
    }
    __syncthreads();

    // ---- AV: out[qi][d] = sum_j w_j * V[idx_j][d] ----
    for (int o = tid; o < TQ*DH; o += 256) {
        int qi = o >> 6, d = o & 63;
        const float* Vb = Vg + (size_t)b*SEQ*DM + h*DH + d;
        float acc = 0.f;
#pragma unroll
        for (int j = 0; j < KS; j++) {
            float w = s_w[qi][j];
            int ii = s_i[qi][j];
            if (ii >= 0) acc += w * Vb[(size_t)ii * DM];
        }
        HO[((size_t)(b*SEQ + q0 + qi)) * DM + h*DH + d] = acc;
    }
}

// ---------------- mean over heads -> dense [B, SEQ, SEQ] ---------------------
__global__ __launch_bounds__(256) void mean_kernel(
    const float* __restrict__ WGT, const int* __restrict__ IDX,
    float* __restrict__ out_attn)
{
    __shared__ float row[SEQ];
    const int q = blockIdx.x, b = blockIdx.y;
    const int tid = threadIdx.x;
    for (int i = tid; i < SEQ; i += 256) row[i] = 0.f;
    __syncthreads();
    for (int h = 0; h < NH; h++) {
        if (tid < KS) {
            size_t off = ((((size_t)b*NH + h)*SEQ) + q) * KS + tid;
            float w = WGT[off];
            int k = IDX[off];
            if (k >= 0 && w > 0.f) row[k] += w * (1.0f / NH);
        }
        __syncthreads();
    }
    float* o = out_attn + ((size_t)b*SEQ + q) * SEQ;
    for (int i = tid; i < SEQ; i += 256) o[i] = row[i];
}

// ---------------- launch -----------------------------------------------------
extern "C" void kernel_launch(void* const* d_in, const int* in_sizes, int n_in,
                              void* d_out, int out_size)
{
    const float* x  = (const float*)d_in[0];
    const float* Wq = (const float*)d_in[1];
    const float* bq = (const float*)d_in[2];
    const float* Wk = (const float*)d_in[3];
    const float* bk = (const float*)d_in[4];
    const float* Wv = (const float*)d_in[5];
    const float* bv = (const float*)d_in[6];
    const float* Wo = (const float*)d_in[7];
    const float* bo = (const float*)d_in[8];

    float *Qp, *Kp, *Vp, *HOp, *Wp; int* Ip;
    cudaGetSymbolAddress((void**)&Qp,  g_Q);
    cudaGetSymbolAddress((void**)&Kp,  g_K);
    cudaGetSymbolAddress((void**)&Vp,  g_V);
    cudaGetSymbolAddress((void**)&HOp, g_HO);
    cudaGetSymbolAddress((void**)&Wp,  g_WGT);
    cudaGetSymbolAddress((void**)&Ip,  g_IDX);

    dim3 ggrid(DM / BN, MROWS / BM);   // (8, 32)

    gemm_kernel<<<ggrid, 256>>>(x, Wq, bq, Qp, MROWS, DM, DM);
    gemm_kernel<<<ggrid, 256>>>(x, Wk, bk, Kp, MROWS, DM, DM);
    gemm_kernel<<<ggrid, 256>>>(x, Wv, bv, Vp, MROWS, DM, DM);

    attn_kernel<<<dim3(SEQ / TQ, NH, BATCH), 256>>>(Qp, Kp, Vp, HOp, Wp, Ip);

    float* yout = (float*)d_out;
    gemm_kernel<<<ggrid, 256>>>(HOp, Wo, bo, yout, MROWS, DM, DM);

    size_t ysz = (size_t)BATCH * SEQ * DM;          // 4,194,304
    size_t asz = (size_t)BATCH * SEQ * SEQ;         // 8,388,608
    if ((size_t)out_size >= ysz + asz) {
        mean_kernel<<<dim3(SEQ, BATCH), 256>>>(Wp, Ip, (float*)d_out + ysz);
    }
}

// round 3
// speedup vs baseline: 1.7058x; 1.6636x over previous
#include <cuda_runtime.h>
#include <cuda_bf16.h>

#define BATCH 2
#define SEQ   2048
#define DM    1024
#define NH    16
#define DH    64
#define KS    32

#define MROWS (BATCH*SEQ)   // 4096
#define FULLM 0xffffffffu
#define NTILE 16            // 2048/128 tiles per side
#define NTRI  136           // lower-triangular tile count

// ---------------- scratch (device globals; no allocation allowed) ----------
__device__ float g_Q [BATCH*SEQ*DM];
__device__ float g_K [BATCH*SEQ*DM];
__device__ float g_V [BATCH*SEQ*DM];
__device__ float g_HO[BATCH*SEQ*DM];
__device__ float g_WGT[BATCH*NH*SEQ*KS];
__device__ int   g_IDX[BATCH*NH*SEQ*KS];
__device__ float g_SC[(size_t)BATCH*NH*SEQ*SEQ];   // 536 MB score scratch

__device__ __forceinline__ float neg_inf() { return __int_as_float(0xff800000); }

// ---------------- GEMM: C[M,N] = A[M,K] @ W[N,K]^T + bias --------------------
#define BM 128
#define BN 128
#define BK 8

__global__ __launch_bounds__(256) void gemm_kernel(
    const float* __restrict__ A, const float* __restrict__ W,
    const float* __restrict__ bias, float* __restrict__ C,
    int M, int N, int K)
{
    __shared__ float As[BK][BM];
    __shared__ float Ws[BK][BN];
    int tid = threadIdx.x;
    int tx = tid & 15, ty = tid >> 4;
    int bm = blockIdx.y * BM, bn = blockIdx.x * BN;

    float acc[8][8];
#pragma unroll
    for (int i = 0; i < 8; i++)
#pragma unroll
        for (int j = 0; j < 8; j++) acc[i][j] = 0.f;

    int lr = tid >> 1;            // 0..127
    int lc = (tid & 1) * 4;       // 0 or 4

    for (int k0 = 0; k0 < K; k0 += BK) {
        float4 av = *(const float4*)(A + (size_t)(bm + lr) * K + k0 + lc);
        float4 wv = *(const float4*)(W + (size_t)(bn + lr) * K + k0 + lc);
        As[lc+0][lr] = av.x; As[lc+1][lr] = av.y; As[lc+2][lr] = av.z; As[lc+3][lr] = av.w;
        Ws[lc+0][lr] = wv.x; Ws[lc+1][lr] = wv.y; Ws[lc+2][lr] = wv.z; Ws[lc+3][lr] = wv.w;
        __syncthreads();
#pragma unroll
        for (int kk = 0; kk < BK; kk++) {
            float4 a0 = *(const float4*)&As[kk][ty*4];
            float4 a1 = *(const float4*)&As[kk][64 + ty*4];
            float4 w0 = *(const float4*)&Ws[kk][tx*4];
            float4 w1 = *(const float4*)&Ws[kk][64 + tx*4];
            float a[8] = {a0.x,a0.y,a0.z,a0.w,a1.x,a1.y,a1.z,a1.w};
            float w[8] = {w0.x,w0.y,w0.z,w0.w,w1.x,w1.y,w1.z,w1.w};
#pragma unroll
            for (int i = 0; i < 8; i++)
#pragma unroll
                for (int j = 0; j < 8; j++)
                    acc[i][j] += a[i] * w[j];
        }
        __syncthreads();
    }

    float4 b0 = *(const float4*)(bias + bn + tx*4);
    float4 b1 = *(const float4*)(bias + bn + 64 + tx*4);
    float bb[8] = {b0.x,b0.y,b0.z,b0.w,b1.x,b1.y,b1.z,b1.w};

#pragma unroll
    for (int i = 0; i < 8; i++) {
        int m = bm + ((i < 4) ? (ty*4 + i) : (64 + ty*4 + i - 4));
        float4 o0 = make_float4(acc[i][0]+bb[0], acc[i][1]+bb[1], acc[i][2]+bb[2], acc[i][3]+bb[3]);
        float4 o1 = make_float4(acc[i][4]+bb[4], acc[i][5]+bb[5], acc[i][6]+bb[6], acc[i][7]+bb[7]);
        *(float4*)(C + (size_t)m * N + bn + tx*4)      = o0;
        *(float4*)(C + (size_t)m * N + bn + 64 + tx*4) = o1;
    }
}

// ---------------- score GEMM: S[q,k] = (Q_row_q . K_row_k) / 8 ---------------
// One block per lower-triangular 128x128 tile of one (b,h). K-dim = 64.
__global__ __launch_bounds__(256) void score_kernel(
    const float* __restrict__ Q, const float* __restrict__ Kg,
    float* __restrict__ SC)
{
    __shared__ float As[16][BM];
    __shared__ float Ws[16][BN];

    const int t = blockIdx.x;
    const int h = blockIdx.y, b = blockIdx.z;
    // map t -> (qt, kt) with qt >= kt
    int qt = (int)((sqrtf(8.f * t + 1.f) - 1.f) * 0.5f);
    while ((qt + 1) * (qt + 2) / 2 <= t) qt++;
    while (qt * (qt + 1) / 2 > t) qt--;
    int kt = t - qt * (qt + 1) / 2;

    const int tid = threadIdx.x;
    const int tx = tid & 15, ty = tid >> 4;
    const int bm = qt * BM, bn = kt * BN;

    float acc[8][8];
#pragma unroll
    for (int i = 0; i < 8; i++)
#pragma unroll
        for (int j = 0; j < 8; j++) acc[i][j] = 0.f;

    const float* Qb = Q  + (size_t)b*SEQ*DM + h*DH;
    const float* Kb = Kg + (size_t)b*SEQ*DM + h*DH;

    int lr = tid >> 1;            // 0..127
    int lc = (tid & 1) * 8;       // 0 or 8

    for (int k0 = 0; k0 < DH; k0 += 16) {
        float4 a0 = *(const float4*)(Qb + (size_t)(bm + lr) * DM + k0 + lc);
        float4 a1 = *(const float4*)(Qb + (size_t)(bm + lr) * DM + k0 + lc + 4);
        float4 w0 = *(const float4*)(Kb + (size_t)(bn + lr) * DM + k0 + lc);
        float4 w1 = *(const float4*)(Kb + (size_t)(bn + lr) * DM + k0 + lc + 4);
        As[lc+0][lr]=a0.x; As[lc+1][lr]=a0.y; As[lc+2][lr]=a0.z; As[lc+3][lr]=a0.w;
        As[lc+4][lr]=a1.x; As[lc+5][lr]=a1.y; As[lc+6][lr]=a1.z; As[lc+7][lr]=a1.w;
        Ws[lc+0][lr]=w0.x; Ws[lc+1][lr]=w0.y; Ws[lc+2][lr]=w0.z; Ws[lc+3][lr]=w0.w;
        Ws[lc+4][lr]=w1.x; Ws[lc+5][lr]=w1.y; Ws[lc+6][lr]=w1.z; Ws[lc+7][lr]=w1.w;
        __syncthreads();
#pragma unroll
        for (int kk = 0; kk < 16; kk++) {
            float4 q0 = *(const float4*)&As[kk][ty*4];
            float4 q1 = *(const float4*)&As[kk][64 + ty*4];
            float4 k0v = *(const float4*)&Ws[kk][tx*4];
            float4 k1v = *(const float4*)&Ws[kk][64 + tx*4];
            float a[8] = {q0.x,q0.y,q0.z,q0.w,q1.x,q1.y,q1.z,q1.w};
            float w[8] = {k0v.x,k0v.y,k0v.z,k0v.w,k1v.x,k1v.y,k1v.z,k1v.w};
#pragma unroll
            for (int i = 0; i < 8; i++)
#pragma unroll
                for (int j = 0; j < 8; j++)
                    acc[i][j] += a[i] * w[j];
        }
        __syncthreads();
    }

    float* Sb = SC + (((size_t)b*NH + h)*SEQ) * SEQ;
#pragma unroll
    for (int i = 0; i < 8; i++) {
        int m = bm + ((i < 4) ? (ty*4 + i) : (64 + ty*4 + i - 4));
        float4 o0 = make_float4(acc[i][0]*.125f, acc[i][1]*.125f, acc[i][2]*.125f, acc[i][3]*.125f);
        float4 o1 = make_float4(acc[i][4]*.125f, acc[i][5]*.125f, acc[i][6]*.125f, acc[i][7]*.125f);
        *(float4*)(Sb + (size_t)m * SEQ + bn + tx*4)      = o0;
        *(float4*)(Sb + (size_t)m * SEQ + bn + 64 + tx*4) = o1;
    }
}

// ---------------- selection: streaming top-32 + softmax + AV -----------------
// One warp per query; 8 warps/block. Low registers -> high occupancy.
__global__ __launch_bounds__(256) void select_kernel(
    const float* __restrict__ SC, const float* __restrict__ Vg,
    float* __restrict__ HO, float* __restrict__ WGT, int* __restrict__ IDX)
{
    const int h = blockIdx.y, b = blockIdx.z;
    const int tid = threadIdx.x;
    const int lane = tid & 31, wid = tid >> 5;
    const int q = blockIdx.x * 8 + wid;
    const float NEG = neg_inf();

    const float* row = SC + ((((size_t)b*NH + h)*SEQ) + q) * SEQ;

    float sv = NEG;
    int   si = 0x7fffffff;

    const int nb = (q + 32) >> 5;    // batches covering keys 0..q
    for (int bi = 0; bi < nb; bi++) {
        int k = (bi << 5) + lane;
        float v = NEG; int ii = 0x7fffffff;
        if (k <= q) { v = row[k]; ii = k; }

        float minv = __shfl_sync(FULLM, sv, 31);
        int   mini = __shfl_sync(FULLM, si, 31);
        bool contend = (v > minv) || (v == minv && v != NEG && ii < mini);
        unsigned m = __ballot_sync(FULLM, contend);
        while (m) {
            int src = __ffs(m) - 1; m &= m - 1;
            float nv = __shfl_sync(FULLM, v,  src);
            int   ni = __shfl_sync(FULLM, ii, src);
            bool better = (sv > nv) || (sv == nv && si < ni);
            unsigned bm2 = __ballot_sync(FULLM, better);
            int p = __popc(bm2);
            float upv = __shfl_up_sync(FULLM, sv, 1);
            int   upi = __shfl_up_sync(FULLM, si, 1);
            if (lane == p)      { sv = nv;  si = ni;  }
            else if (lane > p)  { sv = upv; si = upi; }
        }
    }

    // softmax over selected (sorted descending; lane 0 = max, finite)
    bool valid = (sv != NEG);
    float mx = __shfl_sync(FULLM, sv, 0);
    float e = valid ? expf(sv - mx) : 0.f;
    float tot = e;
#pragma unroll
    for (int o = 16; o; o >>= 1) tot += __shfl_xor_sync(FULLM, tot, o);
    float w = e / tot;
    int iw = valid ? si : -1;

    size_t off = ((((size_t)b*NH + h)*SEQ) + (size_t)q) * KS + lane;
    WGT[off] = w;
    IDX[off] = iw;

    // AV: each lane owns dims (lane, lane+32)
    const float* Vb = Vg + (size_t)b*SEQ*DM + h*DH;
    float acc0 = 0.f, acc1 = 0.f;
#pragma unroll
    for (int j = 0; j < KS; j++) {
        float wj = __shfl_sync(FULLM, w, j);
        int   ij = __shfl_sync(FULLM, iw, j);
        if (ij >= 0) {
            const float* vr = Vb + (size_t)ij * DM;
            acc0 += wj * vr[lane];
            acc1 += wj * vr[lane + 32];
        }
    }
    float* out = HO + ((size_t)(b*SEQ + q)) * DM + h*DH;
    out[lane]      = acc0;
    out[lane + 32] = acc1;
}

// ---------------- mean over heads -> dense [B, SEQ, SEQ] ---------------------
__global__ __launch_bounds__(256) void mean_kernel(
    const float* __restrict__ WGT, const int* __restrict__ IDX,
    float* __restrict__ out_attn)
{
    __shared__ float row[SEQ];
    const int q = blockIdx.x, b = blockIdx.y;
    const int tid = threadIdx.x;
    for (int i = tid; i < SEQ; i += 256) row[i] = 0.f;
    __syncthreads();
    for (int h = 0; h < NH; h++) {
        if (tid < KS) {
            size_t off = ((((size_t)b*NH + h)*SEQ) + q) * KS + tid;
            float w = WGT[off];
            int k = IDX[off];
            if (k >= 0 && w > 0.f) row[k] += w * (1.0f / NH);
        }
        __syncthreads();
    }
    float* o = out_attn + ((size_t)b*SEQ + q) * SEQ;
    for (int i = tid; i < SEQ; i += 256) o[i] = row[i];
}

// ---------------- launch -----------------------------------------------------
extern "C" void kernel_launch(void* const* d_in, const int* in_sizes, int n_in,
                              void* d_out, int out_size)
{
    const float* x  = (const float*)d_in[0];
    const float* Wq = (const float*)d_in[1];
    const float* bq = (const float*)d_in[2];
    const float* Wk = (const float*)d_in[3];
    const float* bk = (const float*)d_in[4];
    const float* Wv = (const float*)d_in[5];
    const float* bv = (const float*)d_in[6];
    const float* Wo = (const float*)d_in[7];
    const float* bo = (const float*)d_in[8];

    float *Qp, *Kp, *Vp, *HOp, *Wp, *Sp; int* Ip;
    cudaGetSymbolAddress((void**)&Qp,  g_Q);
    cudaGetSymbolAddress((void**)&Kp,  g_K);
    cudaGetSymbolAddress((void**)&Vp,  g_V);
    cudaGetSymbolAddress((void**)&HOp, g_HO);
    cudaGetSymbolAddress((void**)&Wp,  g_WGT);
    cudaGetSymbolAddress((void**)&Ip,  g_IDX);
    cudaGetSymbolAddress((void**)&Sp,  g_SC);

    dim3 ggrid(DM / BN, MROWS / BM);   // (8, 32)

    gemm_kernel<<<ggrid, 256>>>(x, Wq, bq, Qp, MROWS, DM, DM);
    gemm_kernel<<<ggrid, 256>>>(x, Wk, bk, Kp, MROWS, DM, DM);
    gemm_kernel<<<ggrid, 256>>>(x, Wv, bv, Vp, MROWS, DM, DM);

    score_kernel<<<dim3(NTRI, NH, BATCH), 256>>>(Qp, Kp, Sp);
    select_kernel<<<dim3(SEQ / 8, NH, BATCH), 256>>>(Sp, Vp, HOp, Wp, Ip);

    float* yout = (float*)d_out;
    gemm_kernel<<<ggrid, 256>>>(HOp, Wo, bo, yout, MROWS, DM, DM);

    size_t ysz = (size_t)BATCH * SEQ * DM;          // 4,194,304
    size_t asz = (size_t)BATCH * SEQ * SEQ;         // 8,388,608
    if ((size_t)out_size >= ysz + asz) {
        mean_kernel<<<dim3(SEQ, BATCH), 256>>>(Wp, Ip, (float*)d_out + ysz);
    }
}